// round 1
// baseline (speedup 1.0000x reference)
#include <cuda_runtime.h>
#include <math.h>

// Problem constants (fixed by the reference)
#define T_STEPS 256
#define BSZ     64
#define DIM     1024
#define N3      (3 * DIM)          // 3072
#define M_TOTAL (T_STEPS * BSZ)    // 16384
#define KSPLIT  4
#define KCH     (DIM / KSPLIT)     // 256

// Scratch (allocation-free rule: __device__ globals)
__device__ float g_xproj[(size_t)M_TOTAL * N3];     // [T,B,3D]  ~192 MiB
__device__ float g_part[KSPLIT * BSZ * N3];         // split-K partials, ~3 MiB
__device__ int   g_dones_is_byte;                   // runtime dtype flag for dones

// ---------------------------------------------------------------------------
// Detect whether `dones` is stored as 1-byte bool or 4-byte int32.
// If int32 little-endian 0/1 values, all bytes at i%4!=0 are zero.
// ---------------------------------------------------------------------------
__global__ void detect_dones_kernel(const unsigned char* __restrict__ p) {
    int nz = 0;
    for (int i = 0; i < 256; i++) {
        if ((i & 3) != 0 && p[i] != 0) nz++;
    }
    g_dones_is_byte = (nz > 0) ? 1 : 0;
}

__device__ __forceinline__ bool read_done(const void* dones, int idx, int is_byte) {
    if (is_byte) return ((const unsigned char*)dones)[idx] != 0;
    return ((const int*)dones)[idx] != 0;
}

// ---------------------------------------------------------------------------
// Phase 1: x_proj[t,b,:] = ins[t,b,:] @ W_i + b_i
// M=16384, K=1024, N=3072. BM=128, BN=64, BK=16, 256 threads, 8x4 per thread.
// ---------------------------------------------------------------------------
#define BM1 128
#define BN1 64
#define BK1 16

__global__ __launch_bounds__(256) void gemm_xproj_kernel(
    const float* __restrict__ A,     // [M, K]
    const float* __restrict__ W,     // [K, N]
    const float* __restrict__ bias)  // [N]
{
    __shared__ __align__(16) float As[BK1][BM1];
    __shared__ __align__(16) float Bs[BK1][BN1];

    const int K = DIM, N = N3;
    const int bn = blockIdx.x;
    const int bm = blockIdx.y;
    const int tid = threadIdx.x;
    const int tx = tid & 15;    // 16 col-groups of 4
    const int ty = tid >> 4;    // 16 row-groups of 8

    float acc[8][4];
#pragma unroll
    for (int i = 0; i < 8; i++)
#pragma unroll
        for (int j = 0; j < 4; j++) acc[i][j] = 0.f;

    const float* Ab = A + (size_t)bm * BM1 * K;
    const float* Wb = W + (size_t)bn * BN1;

    for (int k0 = 0; k0 < K; k0 += BK1) {
        // Load A tile 128x16 (2048 floats, 2 float4 per thread), stored transposed
#pragma unroll
        for (int v = 0; v < 2; v++) {
            int idx = (tid + v * 256) * 4;      // 0..2047
            int r = idx >> 4;                   // row 0..127
            int c = idx & 15;                   // k   {0,4,8,12}
            float4 a4 = *(const float4*)(Ab + (size_t)r * K + k0 + c);
            As[c + 0][r] = a4.x;
            As[c + 1][r] = a4.y;
            As[c + 2][r] = a4.z;
            As[c + 3][r] = a4.w;
        }
        // Load B tile 16x64 (1024 floats, 1 float4 per thread)
        {
            int idx = tid * 4;
            int r = idx >> 6;                   // k row 0..15
            int c = idx & 63;                   // col
            *(float4*)&Bs[r][c] = *(const float4*)(Wb + (size_t)(k0 + r) * N + c);
        }
        __syncthreads();

#pragma unroll
        for (int kk = 0; kk < BK1; kk++) {
            float4 a0 = *(const float4*)&As[kk][ty * 8];
            float4 a1 = *(const float4*)&As[kk][ty * 8 + 4];
            float4 b0 = *(const float4*)&Bs[kk][tx * 4];
            float a[8] = {a0.x, a0.y, a0.z, a0.w, a1.x, a1.y, a1.z, a1.w};
            float b[4] = {b0.x, b0.y, b0.z, b0.w};
#pragma unroll
            for (int i = 0; i < 8; i++)
#pragma unroll
                for (int j = 0; j < 4; j++)
                    acc[i][j] = fmaf(a[i], b[j], acc[i][j]);
        }
        __syncthreads();
    }

#pragma unroll
    for (int i = 0; i < 8; i++) {
        int m = bm * BM1 + ty * 8 + i;
        int n0 = bn * BN1 + tx * 4;
#pragma unroll
        for (int j = 0; j < 4; j++)
            g_xproj[(size_t)m * N + n0 + j] = acc[i][j] + bias[n0 + j];
    }
}

// ---------------------------------------------------------------------------
// Per-step GEMM: G = h_eff @ W_h   ([64,1024] x [1024,3072]) with split-K.
// h_eff[b,k] = done[t,b] ? hiddens[t,b,k] : hprev[b,k]
// BM=64 (all batch), BN=96, K-chunk=256, grid (32, 4) = 128 blocks.
// Each thread: 4(b) x 6(n) accumulators.
// ---------------------------------------------------------------------------
#define BN2 96
#define BK2 16

__global__ __launch_bounds__(256) void gru_gemm_kernel(
    const float* __restrict__ hprev,     // [B, D]
    const float* __restrict__ hiddens,   // [T, B, D]
    const void*  __restrict__ dones,
    int t,
    const float* __restrict__ Wh)        // [D, 3D]
{
    __shared__ __align__(16) float As[BK2][BSZ];
    __shared__ __align__(16) float Bs[BK2][BN2];

    const int bn = blockIdx.x;       // 0..31
    const int kidx = blockIdx.y;     // 0..3
    const int tid = threadIdx.x;
    const int tx = tid & 15;         // 16 col-groups of 6
    const int ty = tid >> 4;         // 16 row-groups of 4
    const int is_byte = g_dones_is_byte;
    const float* hid_t = hiddens + (size_t)t * BSZ * DIM;

    float acc[4][6];
#pragma unroll
    for (int i = 0; i < 4; i++)
#pragma unroll
        for (int j = 0; j < 6; j++) acc[i][j] = 0.f;

    const int kbase = kidx * KCH;

    for (int k0 = kbase; k0 < kbase + KCH; k0 += BK2) {
        // A tile 64x16 (1024 floats, 1 float4 per thread), transposed store,
        // with done-reset applied at load.
        {
            int idx = tid * 4;
            int r = idx >> 4;          // b 0..63
            int c = idx & 15;          // k {0,4,8,12}
            bool dn = read_done(dones, t * BSZ + r, is_byte);
            const float* src = dn ? (hid_t + (size_t)r * DIM)
                                  : (hprev + (size_t)r * DIM);
            float4 a4 = *(const float4*)(src + k0 + c);
            As[c + 0][r] = a4.x;
            As[c + 1][r] = a4.y;
            As[c + 2][r] = a4.z;
            As[c + 3][r] = a4.w;
        }
        // B tile 16x96 (1536 floats, 6 scalar loads per thread)
        for (int i = tid; i < BK2 * BN2; i += 256) {
            int r = i / BN2;
            int c = i - r * BN2;
            Bs[r][c] = Wh[(size_t)(k0 + r) * N3 + bn * BN2 + c];
        }
        __syncthreads();

#pragma unroll
        for (int kk = 0; kk < BK2; kk++) {
            float4 av = *(const float4*)&As[kk][ty * 4];
            float a[4] = {av.x, av.y, av.z, av.w};
            float2 b0 = *(const float2*)&Bs[kk][tx * 6];
            float2 b1 = *(const float2*)&Bs[kk][tx * 6 + 2];
            float2 b2 = *(const float2*)&Bs[kk][tx * 6 + 4];
            float b[6] = {b0.x, b0.y, b1.x, b1.y, b2.x, b2.y};
#pragma unroll
            for (int i = 0; i < 4; i++)
#pragma unroll
                for (int j = 0; j < 6; j++)
                    acc[i][j] = fmaf(a[i], b[j], acc[i][j]);
        }
        __syncthreads();
    }

#pragma unroll
    for (int i = 0; i < 4; i++) {
        int b = ty * 4 + i;
        int n0 = bn * BN2 + tx * 6;
        float* gp = g_part + ((size_t)kidx * BSZ + b) * N3 + n0;
#pragma unroll
        for (int j = 0; j < 6; j++) gp[j] = acc[i][j];
    }
}

// ---------------------------------------------------------------------------
// Per-step fused gates: reduce split-K partials, apply GRU update, write ys[t].
// ---------------------------------------------------------------------------
__global__ __launch_bounds__(256) void gru_fuse_kernel(
    const float* __restrict__ hprev,     // [B, D]
    const float* __restrict__ hiddens,   // [T, B, D]
    const void*  __restrict__ dones,
    int t,
    const float* __restrict__ b_hn,      // [D]
    float* __restrict__ ys)              // [T, B, D]
{
    int idx = blockIdx.x * blockDim.x + threadIdx.x;   // 0 .. B*D-1
    int b = idx >> 10;          // / DIM
    int d = idx & (DIM - 1);
    const int is_byte = g_dones_is_byte;

    bool dn = read_done(dones, t * BSZ + b, is_byte);
    const float* hid_t = hiddens + (size_t)t * BSZ * DIM;
    float h = dn ? hid_t[idx] : hprev[idx];

    float hr = 0.f, hz = 0.f, hn = 0.f;
#pragma unroll
    for (int p = 0; p < KSPLIT; p++) {
        const float* g = g_part + ((size_t)p * BSZ + b) * N3;
        hr += g[d];
        hz += g[DIM + d];
        hn += g[2 * DIM + d];
    }

    const float* xp = g_xproj + ((size_t)t * BSZ + b) * N3;
    float r = 1.f / (1.f + __expf(-(xp[d] + hr)));
    float z = 1.f / (1.f + __expf(-(xp[DIM + d] + hz)));
    float n = tanhf(xp[2 * DIM + d] + r * (hn + b_hn[d]));

    ys[(size_t)t * BSZ * DIM + idx] = (1.f - z) * n + z * h;
}

// ---------------------------------------------------------------------------
// kernel_launch
// Inputs (metadata order): ins, hiddens, dones, init_carry, W_i, W_h, b_i, b_hn
// Output: [final_carry (B*D) | ys (T*B*D)]  (pytree order of the tuple)
// ---------------------------------------------------------------------------
extern "C" void kernel_launch(void* const* d_in, const int* in_sizes, int n_in,
                              void* d_out, int out_size) {
    const float* ins        = (const float*)d_in[0];
    const float* hiddens    = (const float*)d_in[1];
    const void*  dones      = d_in[2];
    const float* init_carry = (const float*)d_in[3];
    const float* W_i        = (const float*)d_in[4];
    const float* W_h        = (const float*)d_in[5];
    const float* b_i        = (const float*)d_in[6];
    const float* b_hn       = (const float*)d_in[7];

    float* out = (float*)d_out;
    float* final_carry = out;                       // [B, D]
    float* ys = out + (size_t)BSZ * DIM;            // [T, B, D]

    // dtype probe for dones (bool8 vs int32)
    detect_dones_kernel<<<1, 1>>>((const unsigned char*)dones);

    // Phase 1: hoisted input projection
    {
        dim3 grid(N3 / BN1, M_TOTAL / BM1);         // (48, 128)
        gemm_xproj_kernel<<<grid, 256>>>(ins, W_i, b_i);
    }

    // Phase 2: sequential scan
    for (int t = 0; t < T_STEPS; t++) {
        const float* hprev = (t == 0) ? init_carry
                                      : (ys + (size_t)(t - 1) * BSZ * DIM);
        dim3 ggrid(N3 / BN2, KSPLIT);               // (32, 4) = 128 blocks
        gru_gemm_kernel<<<ggrid, 256>>>(hprev, hiddens, dones, t, W_h);
        gru_fuse_kernel<<<(BSZ * DIM) / 256, 256>>>(hprev, hiddens, dones, t,
                                                    b_hn, ys);
    }

    // final_carry = ys[T-1]
    cudaMemcpyAsync(final_carry, ys + (size_t)(T_STEPS - 1) * BSZ * DIM,
                    (size_t)BSZ * DIM * sizeof(float),
                    cudaMemcpyDeviceToDevice);
}

// round 2
// speedup vs baseline: 2.0987x; 2.0987x over previous
#include <cuda_runtime.h>
#include <math.h>

// Problem constants
#define T_STEPS 256
#define BSZ     64
#define DIM     1024
#define N3      (3 * DIM)          // 3072
#define M_TOTAL (T_STEPS * BSZ)    // 16384
#define NCTA    128                // persistent scan CTAs (<=148 SMs, 1/SM by smem)
#define NTHR    256

typedef unsigned long long ull;

// Scratch (__device__ globals; allocation-free rule)
__device__ float g_xproj[(size_t)M_TOTAL * N3];     // [T,B,3D] ~192 MiB
__device__ float g_part[4 * BSZ * N3];              // split-K partials
__device__ float g_heff[BSZ * DIM];                 // reset-applied h for current step
__device__ int   g_dones_is_byte;
__device__ unsigned g_bar_count;                    // zero-init; protocol restores 0
__device__ unsigned g_bar_epoch;                    // zero-init; protocol restores 0

// ---------------- packed f32x2 helpers (sm_103a 2x fp32 path) ----------------
__device__ __forceinline__ ull ffma2(ull a, ull b, ull c) {
    ull d;
    asm("fma.rn.f32x2 %0, %1, %2, %3;" : "=l"(d) : "l"(a), "l"(b), "l"(c));
    return d;
}
__device__ __forceinline__ ull pack2(float x, float y) {
    ull d;
    asm("mov.b64 %0, {%1, %2};" : "=l"(d) : "f"(x), "f"(y));
    return d;
}
__device__ __forceinline__ float2 unpack2(ull v) {
    float2 r;
    asm("mov.b64 {%0, %1}, %2;" : "=f"(r.x), "=f"(r.y) : "l"(v));
    return r;
}

// ---------------- dones dtype probe (bool8 vs int32) ----------------
__global__ void detect_dones_kernel(const unsigned char* __restrict__ p) {
    int nz = 0;
    for (int i = 0; i < 256; i++)
        if ((i & 3) != 0 && p[i] != 0) nz++;
    g_dones_is_byte = (nz > 0) ? 1 : 0;
}
__device__ __forceinline__ bool read_done(const void* dones, int idx, int is_byte) {
    if (is_byte) return ((const unsigned char*)dones)[idx] != 0;
    return ((const int*)dones)[idx] != 0;
}

// ---------------------------------------------------------------------------
// Phase 1: x_proj = ins @ W_i + b_i   (M=16384, K=1024, N=3072)
// BM=128, BN=64, BK=16, 256 threads, thread tile 8x4 via f32x2 (8x2 packed).
// ---------------------------------------------------------------------------
#define BM1 128
#define BN1 64
#define BK1 16

__global__ __launch_bounds__(256) void gemm_xproj_kernel(
    const float* __restrict__ A, const float* __restrict__ W,
    const float* __restrict__ bias)
{
    __shared__ __align__(16) float As[BK1][BM1];
    __shared__ __align__(16) float Bs[BK1][BN1];

    const int K = DIM, N = N3;
    const int bn = blockIdx.x, bm = blockIdx.y;
    const int tid = threadIdx.x;
    const int tx = tid & 15;    // 16 col-groups of 4
    const int ty = tid >> 4;    // 16 row-groups of 8

    ull acc[8][2];
#pragma unroll
    for (int i = 0; i < 8; i++) { acc[i][0] = 0ull; acc[i][1] = 0ull; }

    const float* Ab = A + (size_t)bm * BM1 * K;
    const float* Wb = W + (size_t)bn * BN1;

    for (int k0 = 0; k0 < K; k0 += BK1) {
#pragma unroll
        for (int v = 0; v < 2; v++) {
            int idx = (tid + v * 256) * 4;
            int r = idx >> 4;
            int c = idx & 15;
            float4 a4 = *(const float4*)(Ab + (size_t)r * K + k0 + c);
            As[c + 0][r] = a4.x; As[c + 1][r] = a4.y;
            As[c + 2][r] = a4.z; As[c + 3][r] = a4.w;
        }
        {
            int idx = tid * 4;
            int r = idx >> 6;
            int c = idx & 63;
            *(float4*)&Bs[r][c] = *(const float4*)(Wb + (size_t)(k0 + r) * N + c);
        }
        __syncthreads();

#pragma unroll
        for (int kk = 0; kk < BK1; kk++) {
            float4 a0 = *(const float4*)&As[kk][ty * 8];
            float4 a1 = *(const float4*)&As[kk][ty * 8 + 4];
            ull b0 = *(const ull*)&Bs[kk][tx * 4];
            ull b1 = *(const ull*)&Bs[kk][tx * 4 + 2];
            float a[8] = {a0.x, a0.y, a0.z, a0.w, a1.x, a1.y, a1.z, a1.w};
#pragma unroll
            for (int i = 0; i < 8; i++) {
                ull ad = pack2(a[i], a[i]);
                acc[i][0] = ffma2(ad, b0, acc[i][0]);
                acc[i][1] = ffma2(ad, b1, acc[i][1]);
            }
        }
        __syncthreads();
    }

    int n0 = bn * BN1 + tx * 4;
    float4 bv = *(const float4*)&bias[n0];
#pragma unroll
    for (int i = 0; i < 8; i++) {
        int m = bm * BM1 + ty * 8 + i;
        float2 v0 = unpack2(acc[i][0]);
        float2 v1 = unpack2(acc[i][1]);
        v0.x += bv.x; v0.y += bv.y; v1.x += bv.z; v1.y += bv.w;
        float4 o; o.x = v0.x; o.y = v0.y; o.z = v1.x; o.w = v1.y;
        *(float4*)&g_xproj[(size_t)m * N + n0] = o;
    }
}

// ---------------------------------------------------------------------------
// Persistent scan kernel: 128 CTAs, 2 grid barriers per step.
// CTA (bn,kidx): phase A computes partial[b, bn*96..+96) over K-chunk kidx,
// with W_h slice resident in SMEM the whole scan and h-chunk staged in SMEM.
// Phase B: reduce 4 partials, gates, write ys[t] (+ pre-gated h for t+1).
// ---------------------------------------------------------------------------
__device__ __forceinline__ void grid_barrier(unsigned* s_epoch, bool last) {
    __threadfence();                 // push my writes + CCTL.IVALL (L1 flush)
    __syncthreads();
    if (threadIdx.x == 0) {
        unsigned my = *s_epoch;
        unsigned prev = atomicAdd(&g_bar_count, 1u);
        if (prev == NCTA - 1) {
            g_bar_count = 0;
            __threadfence();
            atomicExch(&g_bar_epoch, last ? 0u : (my + 1u));
        } else {
            volatile unsigned* ep = &g_bar_epoch;
            while (*ep == my) { __nanosleep(64); }
            __threadfence();
        }
        *s_epoch = my + 1u;
    }
    __syncthreads();
}

#define SMEM_BYTES ((256 * 96 + BSZ * 256) * 4)   // Bs + Hs = 163840 B -> 1 CTA/SM

__global__ __launch_bounds__(NTHR, 1) void scan_kernel(
    const float* __restrict__ hiddens,   // [T,B,D]
    const void*  __restrict__ dones,
    const float* __restrict__ init_carry,
    const float* __restrict__ W_h,       // [D, 3D]
    const float* __restrict__ b_hn,      // [D]
    float* __restrict__ out)             // [final (B*D) | ys (T*B*D)]
{
    extern __shared__ float smem[];
    float* Bs = smem;                    // [256][96] W_h slice, k-major
    float* Hs = smem + 256 * 96;         // [64][256] h chunk, b-major
    __shared__ unsigned s_epoch;

    const int tid = threadIdx.x;
    const int cta = blockIdx.x;
    const int bn = cta & 31;             // n-slice (96 cols)
    const int kidx = cta >> 5;           // k-chunk (256)
    const int kbase = kidx * 256;
    const int tx = tid & 15;             // 6-col groups
    const int ty = tid >> 4;             // 4-row groups
    const int is_byte = g_dones_is_byte;
    float* ys = out + (size_t)BSZ * DIM;

    if (tid == 0) s_epoch = 0;

    // W_h slice -> SMEM once (reused for all 256 steps)
    for (int i = tid; i < 256 * 24; i += NTHR) {
        int k = i / 24, c4 = (i % 24) * 4;
        *(float4*)&Bs[k * 96 + c4] =
            *(const float4*)&W_h[(size_t)(kbase + k) * N3 + bn * 96 + c4];
    }

    // initial h_eff (t=0 reset applied)
    {
        int e = cta * 512 + tid * 2;
        int b = e >> 10, d = e & 1023;
        bool dn = read_done(dones, b, is_byte);
        const float* src = dn ? (hiddens + (size_t)b * DIM)
                              : (init_carry + (size_t)b * DIM);
        float2 v = *(const float2*)&src[d];
        *(float2*)&g_heff[b * DIM + d] = v;
    }
    grid_barrier(&s_epoch, false);

    for (int t = 0; t < T_STEPS; t++) {
        // ---- phase A: stage h chunk, then 64x96xK256 partial GEMM ----
        for (int i = tid; i < BSZ * 64; i += NTHR) {      // 4096 float4
            int b = i >> 6;
            int c4 = (i & 63) * 4;
            float4 v = __ldcg((const float4*)&g_heff[b * DIM + kbase + c4]);
            *(float4*)&Hs[b * 256 + c4] = v;
        }
        __syncthreads();

        ull acc[4][3];
#pragma unroll
        for (int i = 0; i < 4; i++)
#pragma unroll
            for (int j = 0; j < 3; j++) acc[i][j] = 0ull;

        const float* hrow0 = Hs + (ty * 4 + 0) * 256;
        const float* hrow1 = Hs + (ty * 4 + 1) * 256;
        const float* hrow2 = Hs + (ty * 4 + 2) * 256;
        const float* hrow3 = Hs + (ty * 4 + 3) * 256;
        const float* bcol = Bs + tx * 6;

#pragma unroll 8
        for (int k = 0; k < 256; k++) {
            ull b0 = *(const ull*)&bcol[k * 96 + 0];
            ull b1 = *(const ull*)&bcol[k * 96 + 2];
            ull b2 = *(const ull*)&bcol[k * 96 + 4];
            ull a0 = pack2(hrow0[k], hrow0[k]);
            ull a1 = pack2(hrow1[k], hrow1[k]);
            ull a2 = pack2(hrow2[k], hrow2[k]);
            ull a3 = pack2(hrow3[k], hrow3[k]);
            acc[0][0] = ffma2(a0, b0, acc[0][0]);
            acc[0][1] = ffma2(a0, b1, acc[0][1]);
            acc[0][2] = ffma2(a0, b2, acc[0][2]);
            acc[1][0] = ffma2(a1, b0, acc[1][0]);
            acc[1][1] = ffma2(a1, b1, acc[1][1]);
            acc[1][2] = ffma2(a1, b2, acc[1][2]);
            acc[2][0] = ffma2(a2, b0, acc[2][0]);
            acc[2][1] = ffma2(a2, b1, acc[2][1]);
            acc[2][2] = ffma2(a2, b2, acc[2][2]);
            acc[3][0] = ffma2(a3, b0, acc[3][0]);
            acc[3][1] = ffma2(a3, b1, acc[3][1]);
            acc[3][2] = ffma2(a3, b2, acc[3][2]);
        }

#pragma unroll
        for (int i = 0; i < 4; i++) {
            float* gp = g_part + ((size_t)(kidx * BSZ + ty * 4 + i)) * N3
                        + bn * 96 + tx * 6;
#pragma unroll
            for (int j = 0; j < 3; j++) {
                float2 v = unpack2(acc[i][j]);
                *(float2*)&gp[2 * j] = v;
            }
        }
        grid_barrier(&s_epoch, false);

        // ---- phase B: reduce partials + gates + write ys[t], h_eff[t+1] ----
        {
            int e = cta * 512 + tid * 2;
            int b = e >> 10, d = e & 1023;
            float2 pr = {0.f, 0.f}, pz = {0.f, 0.f}, pn = {0.f, 0.f};
#pragma unroll
            for (int k = 0; k < 4; k++) {
                const float* g = g_part + (size_t)(k * BSZ + b) * N3;
                float2 v;
                v = __ldcg((const float2*)&g[d]);            pr.x += v.x; pr.y += v.y;
                v = __ldcg((const float2*)&g[DIM + d]);      pz.x += v.x; pz.y += v.y;
                v = __ldcg((const float2*)&g[2 * DIM + d]);  pn.x += v.x; pn.y += v.y;
            }
            const float* xp = g_xproj + (size_t)(t * BSZ + b) * N3;
            float2 xr = *(const float2*)&xp[d];
            float2 xz = *(const float2*)&xp[DIM + d];
            float2 xn = *(const float2*)&xp[2 * DIM + d];
            float2 h2 = __ldcg((const float2*)&g_heff[b * DIM + d]);
            float2 bh = *(const float2*)&b_hn[d];

            float rx = 1.f / (1.f + __expf(-(xr.x + pr.x)));
            float ry = 1.f / (1.f + __expf(-(xr.y + pr.y)));
            float zx = 1.f / (1.f + __expf(-(xz.x + pz.x)));
            float zy = 1.f / (1.f + __expf(-(xz.y + pz.y)));
            float nx = tanhf(xn.x + rx * (pn.x + bh.x));
            float ny = tanhf(xn.y + ry * (pn.y + bh.y));
            float2 hnew;
            hnew.x = (1.f - zx) * nx + zx * h2.x;
            hnew.y = (1.f - zy) * ny + zy * h2.y;

            *(float2*)&ys[((size_t)t * BSZ + b) * DIM + d] = hnew;
            if (t == T_STEPS - 1) {
                *(float2*)&out[b * DIM + d] = hnew;       // final_carry
            } else {
                bool dn = read_done(dones, (t + 1) * BSZ + b, is_byte);
                float2 he = hnew;
                if (dn)
                    he = *(const float2*)&hiddens[((size_t)(t + 1) * BSZ + b) * DIM + d];
                *(float2*)&g_heff[b * DIM + d] = he;
            }
        }
        grid_barrier(&s_epoch, t == T_STEPS - 1);
    }
}

// ---------------------------------------------------------------------------
extern "C" void kernel_launch(void* const* d_in, const int* in_sizes, int n_in,
                              void* d_out, int out_size) {
    const float* ins        = (const float*)d_in[0];
    const float* hiddens    = (const float*)d_in[1];
    const void*  dones      = d_in[2];
    const float* init_carry = (const float*)d_in[3];
    const float* W_i        = (const float*)d_in[4];
    const float* W_h        = (const float*)d_in[5];
    const float* b_i        = (const float*)d_in[6];
    const float* b_hn       = (const float*)d_in[7];
    float* out = (float*)d_out;

    cudaFuncSetAttribute(scan_kernel,
                         cudaFuncAttributeMaxDynamicSharedMemorySize, SMEM_BYTES);

    detect_dones_kernel<<<1, 1>>>((const unsigned char*)dones);

    dim3 grid1(N3 / BN1, M_TOTAL / BM1);    // (48, 128)
    gemm_xproj_kernel<<<grid1, 256>>>(ins, W_i, b_i);

    scan_kernel<<<NCTA, NTHR, SMEM_BYTES>>>(hiddens, dones, init_carry,
                                            W_h, b_hn, out);
}